// round 16
// baseline (speedup 1.0000x reference)
#include <cuda_runtime.h>
#include <cuda_fp16.h>

#define NN 50000
#define EE 800000
#define ET (EE + NN)
#define CH 64

// ---------------- scratch (static device globals; no allocation) ----------------
__device__ __align__(256) __half g_h[(size_t)NN * CH];    // gemm out fp16 (row=128B)
__device__ __align__(256) __half g_oh[(size_t)NN * CH];   // agg out fp16, pre-swizzled
__device__ __align__(256) __half g_xh[(size_t)NN * 128];  // layer-1 input fp16, pre-swizzled
__device__ __align__(256) __half g_wt1[64 * 128];         // W1^T fp16 pre-swizzled
__device__ __align__(256) __half g_wt2[64 * 64];
__device__ __align__(256) __half g_wt3[64 * 64];
__device__ float g_as[NN];
__device__ float g_ad[NN];
__device__ int   g_deg[NN];
__device__ int   g_cur[NN];
__device__ int   g_off[NN + 1];
__device__ unsigned long long g_desc[256];   // lookback descriptors {flag<<32 | sum}
__device__ int   g_ssrc[ET];

// ---------------- static stream/event resources ----------------
static cudaStream_t g_s2;
static cudaEvent_t g_ef, g_ej;
static bool g_fork_ok = false;
namespace {
struct StreamInit {
    StreamInit() {
        g_fork_ok =
            cudaStreamCreateWithFlags(&g_s2, cudaStreamNonBlocking) == cudaSuccess &&
            cudaEventCreateWithFlags(&g_ef, cudaEventDisableTiming) == cudaSuccess &&
            cudaEventCreateWithFlags(&g_ej, cudaEventDisableTiming) == cudaSuccess;
    }
};
StreamInit g_si;
}

// ---------------- fp16 precompute: x and weights ----------------
__global__ void conv_kernel(const float* __restrict__ x,
                            const float* __restrict__ W1,
                            const float* __restrict__ W2,
                            const float* __restrict__ W3, int n) {
    int gt = blockIdx.x * blockDim.x + threadIdx.x;
    int gstride = gridDim.x * blockDim.x;

    for (int idx = gt; idx < n * 16; idx += gstride) {
        int row = idx >> 4, u = idx & 15;
        const float4* xp = (const float4*)(x + (size_t)row * 128 + u * 8);
        float4 v0 = xp[0], v1 = xp[1];
        union { __half2 h[4]; uint4 q; } pk;
        pk.h[0] = __floats2half2_rn(v0.x, v0.y);
        pk.h[1] = __floats2half2_rn(v0.z, v0.w);
        pk.h[2] = __floats2half2_rn(v1.x, v1.y);
        pk.h[3] = __floats2half2_rn(v1.z, v1.w);
        *(uint4*)&g_xh[((size_t)row * 16 + (u ^ (row & 7))) * 8] = pk.q;
    }
    for (int idx = gt; idx < 64 * 16; idx += gstride) {   // W1^T (CU=16)
        int nn = idx >> 4, u = idx & 15;
        union { __half2 h[4]; uint4 q; } pk;
        #pragma unroll
        for (int j = 0; j < 4; j++) {
            float w0 = W1[(size_t)(u * 8 + j * 2) * CH + nn];
            float w1 = W1[(size_t)(u * 8 + j * 2 + 1) * CH + nn];
            pk.h[j] = __floats2half2_rn(w0, w1);
        }
        *(uint4*)&g_wt1[(nn * 16 + (u ^ (nn & 7))) * 8] = pk.q;
    }
    for (int idx = gt; idx < 64 * 8 * 2; idx += gstride) {  // W2^T + W3^T (CU=8)
        int which = idx >= 64 * 8;
        int id2 = idx - which * 64 * 8;
        int nn = id2 >> 3, u = id2 & 7;
        const float* W = which ? W3 : W2;
        union { __half2 h[4]; uint4 q; } pk;
        #pragma unroll
        for (int j = 0; j < 4; j++) {
            float w0 = W[(size_t)(u * 8 + j * 2) * CH + nn];
            float w1 = W[(size_t)(u * 8 + j * 2 + 1) * CH + nn];
            pk.h[j] = __floats2half2_rn(w0, w1);
        }
        __half* dst = which ? g_wt3 : g_wt2;
        *(uint4*)&dst[(nn * 8 + (u ^ (nn & 7))) * 8] = pk.q;
    }
}

// ---------------- CSR build chain ----------------
__global__ void zero_kernel(int n) {
    int gt = blockIdx.x * blockDim.x + threadIdx.x;
    int stride = gridDim.x * blockDim.x;
    for (int i = gt; i < n; i += stride)
        g_deg[i] = 1;   // self-loop pre-counted
    if (gt < 256) g_desc[gt] = 0;
}

__global__ void count_kernel(const int* __restrict__ ei, int E, int n) {
    int gt = blockIdx.x * blockDim.x + threadIdx.x;
    int gstride = gridDim.x * blockDim.x;
    int E4 = E >> 2;
    for (int q = gt; q < E4; q += gstride) {
        int4 d4 = *(const int4*)&ei[E + q * 4];
        atomicAdd(&g_deg[d4.x], 1);
        atomicAdd(&g_deg[d4.y], 1);
        atomicAdd(&g_deg[d4.z], 1);
        atomicAdd(&g_deg[d4.w], 1);
    }
    for (int e = E4 * 4 + gt; e < E; e += gstride)
        atomicAdd(&g_deg[ei[E + e]], 1);
}

// single-pass decoupled-lookback exclusive scan: g_deg -> g_off (+g_cur, +g_off[n])
__global__ void scan_lb_kernel(int n) {
    __shared__ int wsum[8];
    __shared__ int wpre[8];
    __shared__ int s_prefix;
    int tid = threadIdx.x;
    int tile = blockIdx.x;
    int i = tile * 256 + tid;
    int lane = tid & 31, wid = tid >> 5;

    int v = (i < n) ? g_deg[i] : 0;
    int incl = v;
    #pragma unroll
    for (int off = 1; off < 32; off <<= 1) {
        int t = __shfl_up_sync(0xffffffffu, incl, off);
        if (lane >= off) incl += t;
    }
    if (lane == 31) wsum[wid] = incl;
    __syncthreads();
    if (tid == 0) {
        int run = 0;
        #pragma unroll
        for (int w = 0; w < 8; w++) { wpre[w] = run; run += wsum[w]; }
        int total = run;
        // publish + lookback (flag and value in ONE 64-bit word: no fence needed)
        if (tile == 0) {
            atomicExch(&g_desc[0], (2ULL << 32) | (unsigned)total);
            s_prefix = 0;
        } else {
            atomicExch(&g_desc[tile], (1ULL << 32) | (unsigned)total);
            int pre = 0;
            int t = tile - 1;
            while (true) {
                unsigned long long d = atomicAdd(&g_desc[t], 0ULL);
                unsigned flag = (unsigned)(d >> 32);
                if (flag == 0) continue;           // predecessor not ready
                pre += (int)(unsigned)d;
                if (flag == 2u) break;             // inclusive prefix found
                t--;
            }
            atomicExch(&g_desc[tile], (2ULL << 32) | (unsigned)(pre + total));
            s_prefix = pre;
        }
    }
    __syncthreads();
    int off = s_prefix + wpre[wid] + incl - v;
    if (i < n) {
        g_off[i] = off;
        g_cur[i] = off;
        if (i == n - 1) g_off[n] = off + v;
    }
}

__global__ void fill_kernel(const int* __restrict__ ei, int E, int n) {
    int gt = blockIdx.x * blockDim.x + threadIdx.x;
    int gstride = gridDim.x * blockDim.x;
    int E4 = E >> 2;
    for (int q = gt; q < E4; q += gstride) {
        int4 s4 = *(const int4*)&ei[q * 4];
        int4 d4 = *(const int4*)&ei[E + q * 4];
        int p0 = atomicAdd(&g_cur[d4.x], 1);
        int p1 = atomicAdd(&g_cur[d4.y], 1);
        int p2 = atomicAdd(&g_cur[d4.z], 1);
        int p3 = atomicAdd(&g_cur[d4.w], 1);
        g_ssrc[p0] = s4.x;
        g_ssrc[p1] = s4.y;
        g_ssrc[p2] = s4.z;
        g_ssrc[p3] = s4.w;
    }
    for (int e = E4 * 4 + gt; e < E; e += gstride) {
        int p = atomicAdd(&g_cur[ei[E + e]], 1);
        g_ssrc[p] = ei[e];
    }
    for (int i = gt; i < n; i += gstride) {           // self-loops
        int p = atomicAdd(&g_cur[i], 1);
        g_ssrc[p] = i;
    }
}

// ---------------- tensor-core GEMM (HMMA m16n8k16, ldmatrix A+B) + fused alpha ----------------
template <int CIN>
__global__ __launch_bounds__(256, 3) void gemm_alpha_kernel(
        int sel, const float* __restrict__ avs, const float* __restrict__ avd, int n) {
    constexpr int CU = CIN / 8;
    __shared__ __half Xs[128 * CIN];
    __shared__ __half Ws[64 * CIN];

    const __half* Xh = (sel == 0) ? g_xh : g_oh;
    const __half* Wt = (sel == 0) ? g_wt1 : ((sel == 1) ? g_wt2 : g_wt3);

    int tid = threadIdx.x;
    int lane = tid & 31;
    int wid = tid >> 5;
    int m0 = blockIdx.x * 128;

    if (m0 + 128 <= n) {
        const uint4* src = (const uint4*)(Xh + (size_t)m0 * CIN);
        uint4* dst = (uint4*)Xs;
        #pragma unroll
        for (int i = 0; i < 128 * CU / 256; i++)
            dst[tid + i * 256] = src[tid + i * 256];
    } else {
        for (int idx = tid; idx < 128 * CU; idx += 256) {
            int row = idx / CU, u = idx - row * CU;
            int rowc = min(m0 + row, n - 1);
            *(uint4*)&Xs[(size_t)idx * 8] = *(const uint4*)&Xh[((size_t)rowc * CU + u) * 8];
        }
    }
    {
        const uint4* src = (const uint4*)Wt;
        uint4* dst = (uint4*)Ws;
        #pragma unroll
        for (int i = 0; i < 64 * CU / 256; i++)
            dst[tid + i * 256] = src[tid + i * 256];
    }
    __syncthreads();

    unsigned xsb, wsb;
    {
        unsigned long long t;
        asm("cvta.to.shared.u64 %0, %1;" : "=l"(t) : "l"(Xs)); xsb = (unsigned)t;
        asm("cvta.to.shared.u64 %0, %1;" : "=l"(t) : "l"(Ws)); wsb = (unsigned)t;
    }

    float c[8][4];
    #pragma unroll
    for (int t = 0; t < 8; t++) { c[t][0] = c[t][1] = c[t][2] = c[t][3] = 0.f; }

    int arow = lane & 15;
    int aub = lane >> 4;
    // B ldmatrix addressing: lane -> (matrix m = lane>>3, row r = lane&7)
    int br = lane & 7;
    int bt_half = (lane >> 4) & 1;      // tile parity within group g
    int bku_sel = (lane >> 3) & 1;      // ku parity

    #pragma unroll
    for (int ks = 0; ks < CIN / 16; ks++) {
        unsigned a0, a1, a2, a3;
        int au = (ks * 2 + aub) ^ (arow & 7);
        unsigned aaddr = xsb + ((wid * 16 + arow) * CU + au) * 16;
        asm volatile("ldmatrix.sync.aligned.m8n8.x4.shared.b16 {%0,%1,%2,%3}, [%4];"
                     : "=r"(a0), "=r"(a1), "=r"(a2), "=r"(a3) : "r"(aaddr));

        unsigned bf[4][4];
        #pragma unroll
        for (int g = 0; g < 4; g++) {
            int t = g * 2 + bt_half;
            int ku = 2 * ks + bku_sel;
            int nrow = t * 8 + br;
            unsigned baddr = wsb + ((nrow * CU + (ku ^ br)) << 4);
            asm volatile("ldmatrix.sync.aligned.m8n8.x4.shared.b16 {%0,%1,%2,%3}, [%4];"
                         : "=r"(bf[g][0]), "=r"(bf[g][1]), "=r"(bf[g][2]), "=r"(bf[g][3])
                         : "r"(baddr));
        }
        #pragma unroll
        for (int t = 0; t < 8; t++) {
            int g = t >> 1, h = (t & 1) * 2;
            asm volatile("mma.sync.aligned.m16n8k16.row.col.f32.f16.f16.f32 "
                         "{%0,%1,%2,%3}, {%4,%5,%6,%7}, {%8,%9}, {%0,%1,%2,%3};"
                         : "+f"(c[t][0]), "+f"(c[t][1]), "+f"(c[t][2]), "+f"(c[t][3])
                         : "r"(a0), "r"(a1), "r"(a2), "r"(a3),
                           "r"(bf[g][h]), "r"(bf[g][h + 1]));
        }
    }

    int r0 = m0 + wid * 16 + (lane >> 2);
    int r1 = r0 + 8;
    float psA = 0.f, pdA = 0.f, psB = 0.f, pdB = 0.f;
    #pragma unroll
    for (int t = 0; t < 8; t++) {
        int col = t * 8 + (lane & 3) * 2;
        float as0 = avs[col], as1 = avs[col + 1];
        float ad0 = avd[col], ad1 = avd[col + 1];
        psA += c[t][0] * as0 + c[t][1] * as1;
        pdA += c[t][0] * ad0 + c[t][1] * ad1;
        psB += c[t][2] * as0 + c[t][3] * as1;
        pdB += c[t][2] * ad0 + c[t][3] * ad1;
        if (r0 < n)
            *(__half2*)((char*)g_h + ((size_t)r0 << 7) + col * 2) = __floats2half2_rn(c[t][0], c[t][1]);
        if (r1 < n)
            *(__half2*)((char*)g_h + ((size_t)r1 << 7) + col * 2) = __floats2half2_rn(c[t][2], c[t][3]);
    }
    #pragma unroll
    for (int o = 1; o <= 2; o <<= 1) {
        psA += __shfl_xor_sync(0xffffffffu, psA, o);
        pdA += __shfl_xor_sync(0xffffffffu, pdA, o);
        psB += __shfl_xor_sync(0xffffffffu, psB, o);
        pdB += __shfl_xor_sync(0xffffffffu, pdB, o);
    }
    if ((lane & 3) == 0) {
        if (r0 < n) { g_as[r0] = psA; g_ad[r0] = pdA; }
        if (r1 < n) { g_as[r1] = psB; g_ad[r1] = pdB; }
    }
}

// ---------------- segment softmax + weighted aggregation (fp16 gather) ----------------
__global__ void agg_kernel(const float* __restrict__ bias,
                           float* __restrict__ dout, int n, int mode) {
    int lane = threadIdx.x & 31;
    int qid = lane >> 3;
    int q = lane & 7;
    int gw = (blockIdx.x * blockDim.x + threadIdx.x) >> 5;
    int nw = (gridDim.x * blockDim.x) >> 5;

    for (int d = gw; d < n; d += nw) {
        int beg = g_off[d], end = g_off[d + 1];
        float adv = g_ad[d];

        float acc[8];
        #pragma unroll
        for (int i = 0; i < 8; i++) acc[i] = 0.f;
        float denp = 0.f;

        for (int base = beg; base < end; base += 32) {
            int j = base + lane;
            int s = 0;
            float w = 0.f;
            if (j < end) {
                s = g_ssrc[j];
                float e = g_as[s] + adv;
                e = e > 0.f ? e : 0.2f * e;
                w = __expf(e);
            }
            denp += w;
            int cnt = min(32, end - base);
            #pragma unroll 4
            for (int k = 0; k < cnt; k += 4) {
                int e = k + qid;
                int   sk = __shfl_sync(0xffffffffu, s, e & 31);
                float wk = __shfl_sync(0xffffffffu, w, e & 31);
                if (e >= cnt) wk = 0.f;
                uint4 u = *(const uint4*)((const char*)g_h + ((size_t)sk << 7) + (q << 4));
                float2 f0 = __half22float2(*(__half2*)&u.x);
                float2 f1 = __half22float2(*(__half2*)&u.y);
                float2 f2 = __half22float2(*(__half2*)&u.z);
                float2 f3 = __half22float2(*(__half2*)&u.w);
                acc[0] = fmaf(wk, f0.x, acc[0]);
                acc[1] = fmaf(wk, f0.y, acc[1]);
                acc[2] = fmaf(wk, f1.x, acc[2]);
                acc[3] = fmaf(wk, f1.y, acc[3]);
                acc[4] = fmaf(wk, f2.x, acc[4]);
                acc[5] = fmaf(wk, f2.y, acc[5]);
                acc[6] = fmaf(wk, f3.x, acc[6]);
                acc[7] = fmaf(wk, f3.y, acc[7]);
            }
        }
        #pragma unroll
        for (int i = 0; i < 8; i++) {
            acc[i] += __shfl_xor_sync(0xffffffffu, acc[i], 8);
            acc[i] += __shfl_xor_sync(0xffffffffu, acc[i], 16);
        }
        float den = denp;
        #pragma unroll
        for (int o = 16; o; o >>= 1) den += __shfl_xor_sync(0xffffffffu, den, o);

        if (qid == 0) {
            float inv = 1.f / den;
            const float4* b4 = (const float4*)bias;
            float4 bv0 = b4[q * 2], bv1 = b4[q * 2 + 1];
            float4 o0, o1;
            o0.x = acc[0] * inv + bv0.x;
            o0.y = acc[1] * inv + bv0.y;
            o0.z = acc[2] * inv + bv0.z;
            o0.w = acc[3] * inv + bv0.w;
            o1.x = acc[4] * inv + bv1.x;
            o1.y = acc[5] * inv + bv1.y;
            o1.z = acc[6] * inv + bv1.z;
            o1.w = acc[7] * inv + bv1.w;
            if (mode == 0) {  // ELU -> fp16 pre-swizzled g_oh
                o0.x = o0.x > 0.f ? o0.x : (__expf(o0.x) - 1.f);
                o0.y = o0.y > 0.f ? o0.y : (__expf(o0.y) - 1.f);
                o0.z = o0.z > 0.f ? o0.z : (__expf(o0.z) - 1.f);
                o0.w = o0.w > 0.f ? o0.w : (__expf(o0.w) - 1.f);
                o1.x = o1.x > 0.f ? o1.x : (__expf(o1.x) - 1.f);
                o1.y = o1.y > 0.f ? o1.y : (__expf(o1.y) - 1.f);
                o1.z = o1.z > 0.f ? o1.z : (__expf(o1.z) - 1.f);
                o1.w = o1.w > 0.f ? o1.w : (__expf(o1.w) - 1.f);
                union { __half2 h[4]; uint4 qv; } ph;
                ph.h[0] = __floats2half2_rn(o0.x, o0.y);
                ph.h[1] = __floats2half2_rn(o0.z, o0.w);
                ph.h[2] = __floats2half2_rn(o1.x, o1.y);
                ph.h[3] = __floats2half2_rn(o1.z, o1.w);
                *(uint4*)&g_oh[((size_t)d * 8 + (q ^ (d & 7))) * 8] = ph.qv;
            } else {
                float4* orow = (float4*)(dout + (size_t)d * CH);
                orow[q * 2]     = o0;
                orow[q * 2 + 1] = o1;
            }
        }
    }
}

// ---------------- launch ----------------
extern "C" void kernel_launch(void* const* d_in, const int* in_sizes, int n_in,
                              void* d_out, int out_size) {
    const float* x     = (const float*)d_in[0];
    const int*   ei    = (const int*)d_in[1];
    const float* W1    = (const float*)d_in[2];
    const float* asr1  = (const float*)d_in[3];
    const float* adt1  = (const float*)d_in[4];
    const float* b1    = (const float*)d_in[5];
    const float* W2    = (const float*)d_in[6];
    const float* asr2  = (const float*)d_in[7];
    const float* adt2  = (const float*)d_in[8];
    const float* b2    = (const float*)d_in[9];
    const float* W3    = (const float*)d_in[10];
    const float* asr3  = (const float*)d_in[11];
    const float* adt3  = (const float*)d_in[12];
    const float* b3    = (const float*)d_in[13];

    int n = in_sizes[0] / 128;   // 50000
    int E = in_sizes[1] / 2;     // 800000
    float* dout = (float*)d_out;

    int nb = (n + 255) / 256;
    int aggGrid = (n * 32 + 255) / 256;
    int gemmGrid = (n + 127) / 128;

    bool two = g_fork_ok;
    cudaStream_t s2 = two ? g_s2 : (cudaStream_t)0;

    if (two) {
        cudaEventRecord(g_ef, 0);
        cudaStreamWaitEvent(s2, g_ef, 0);
    }
    // CSR chain
    zero_kernel<<<96, 256, 0, s2>>>(n);
    count_kernel<<<832, 256, 0, s2>>>(ei, E, n);
    scan_lb_kernel<<<nb, 256, 0, s2>>>(n);
    fill_kernel<<<832, 256, 0, s2>>>(ei, E, n);
    if (two) cudaEventRecord(g_ej, s2);

    // main stream: conversion + layer-1 GEMM (independent of CSR)
    conv_kernel<<<416, 256>>>(x, W1, W2, W3, n);
    gemm_alpha_kernel<128><<<gemmGrid, 256>>>(0, asr1, adt1, n);

    if (two) cudaStreamWaitEvent(0, g_ej, 0);

    agg_kernel<<<aggGrid, 256>>>(b1, dout, n, 0);
    gemm_alpha_kernel<64><<<gemmGrid, 256>>>(1, asr2, adt2, n);
    agg_kernel<<<aggGrid, 256>>>(b2, dout, n, 0);
    gemm_alpha_kernel<64><<<gemmGrid, 256>>>(2, asr3, adt3, n);
    agg_kernel<<<aggGrid, 256>>>(b3, dout, n, 1);
}

// round 17
// speedup vs baseline: 1.0112x; 1.0112x over previous
#include <cuda_runtime.h>
#include <cuda_fp16.h>

#define NN 50000
#define EE 800000
#define ET (EE + NN)
#define CH 64

// ---------------- scratch (static device globals; no allocation) ----------------
__device__ __align__(256) __half g_h[(size_t)NN * CH];    // gemm out fp16 (row=128B)
__device__ __align__(256) __half g_oh[(size_t)NN * CH];   // agg out fp16, pre-swizzled
__device__ __align__(256) __half g_xh[(size_t)NN * 128];  // layer-1 input fp16, pre-swizzled
__device__ __align__(256) __half g_wt1[64 * 128];         // W1^T fp16 pre-swizzled
__device__ __align__(256) __half g_wt2[64 * 64];
__device__ __align__(256) __half g_wt3[64 * 64];
__device__ float g_as[NN];
__device__ float g_ad[NN];
__device__ int   g_deg[NN];
__device__ int   g_cur[NN];
__device__ int   g_off[NN + 1];
__device__ int   g_bsum[256];
__device__ int   g_ssrc[ET];

// ---------------- static stream/event resources ----------------
static cudaStream_t g_s2;
static cudaEvent_t g_ef, g_ej;
static bool g_fork_ok = false;
namespace {
struct StreamInit {
    StreamInit() {
        g_fork_ok =
            cudaStreamCreateWithFlags(&g_s2, cudaStreamNonBlocking) == cudaSuccess &&
            cudaEventCreateWithFlags(&g_ef, cudaEventDisableTiming) == cudaSuccess &&
            cudaEventCreateWithFlags(&g_ej, cudaEventDisableTiming) == cudaSuccess;
    }
};
StreamInit g_si;
}

// ---------------- fp16 precompute: x and weights ----------------
__global__ void conv_kernel(const float* __restrict__ x,
                            const float* __restrict__ W1,
                            const float* __restrict__ W2,
                            const float* __restrict__ W3, int n) {
    int gt = blockIdx.x * blockDim.x + threadIdx.x;
    int gstride = gridDim.x * blockDim.x;

    for (int idx = gt; idx < n * 16; idx += gstride) {
        int row = idx >> 4, u = idx & 15;
        const float4* xp = (const float4*)(x + (size_t)row * 128 + u * 8);
        float4 v0 = xp[0], v1 = xp[1];
        union { __half2 h[4]; uint4 q; } pk;
        pk.h[0] = __floats2half2_rn(v0.x, v0.y);
        pk.h[1] = __floats2half2_rn(v0.z, v0.w);
        pk.h[2] = __floats2half2_rn(v1.x, v1.y);
        pk.h[3] = __floats2half2_rn(v1.z, v1.w);
        *(uint4*)&g_xh[((size_t)row * 16 + (u ^ (row & 7))) * 8] = pk.q;
    }
    for (int idx = gt; idx < 64 * 16; idx += gstride) {   // W1^T (CU=16)
        int nn = idx >> 4, u = idx & 15;
        union { __half2 h[4]; uint4 q; } pk;
        #pragma unroll
        for (int j = 0; j < 4; j++) {
            float w0 = W1[(size_t)(u * 8 + j * 2) * CH + nn];
            float w1 = W1[(size_t)(u * 8 + j * 2 + 1) * CH + nn];
            pk.h[j] = __floats2half2_rn(w0, w1);
        }
        *(uint4*)&g_wt1[(nn * 16 + (u ^ (nn & 7))) * 8] = pk.q;
    }
    for (int idx = gt; idx < 64 * 8 * 2; idx += gstride) {  // W2^T + W3^T (CU=8)
        int which = idx >= 64 * 8;
        int id2 = idx - which * 64 * 8;
        int nn = id2 >> 3, u = id2 & 7;
        const float* W = which ? W3 : W2;
        union { __half2 h[4]; uint4 q; } pk;
        #pragma unroll
        for (int j = 0; j < 4; j++) {
            float w0 = W[(size_t)(u * 8 + j * 2) * CH + nn];
            float w1 = W[(size_t)(u * 8 + j * 2 + 1) * CH + nn];
            pk.h[j] = __floats2half2_rn(w0, w1);
        }
        __half* dst = which ? g_wt3 : g_wt2;
        *(uint4*)&dst[(nn * 8 + (u ^ (nn & 7))) * 8] = pk.q;
    }
}

// ---------------- CSR build chain ----------------
__global__ void zero_kernel(int n) {
    int stride = gridDim.x * blockDim.x;
    for (int i = blockIdx.x * blockDim.x + threadIdx.x; i < n; i += stride)
        g_deg[i] = 1;   // self-loop pre-counted
}

__global__ void count_kernel(const int* __restrict__ ei, int E, int n) {
    int gt = blockIdx.x * blockDim.x + threadIdx.x;
    int gstride = gridDim.x * blockDim.x;
    int E8 = E >> 3;
    for (int q = gt; q < E8; q += gstride) {
        int4 a4 = *(const int4*)&ei[E + q * 8];
        int4 b4 = *(const int4*)&ei[E + q * 8 + 4];
        atomicAdd(&g_deg[a4.x], 1);
        atomicAdd(&g_deg[a4.y], 1);
        atomicAdd(&g_deg[a4.z], 1);
        atomicAdd(&g_deg[a4.w], 1);
        atomicAdd(&g_deg[b4.x], 1);
        atomicAdd(&g_deg[b4.y], 1);
        atomicAdd(&g_deg[b4.z], 1);
        atomicAdd(&g_deg[b4.w], 1);
    }
    for (int e = E8 * 8 + gt; e < E; e += gstride)
        atomicAdd(&g_deg[ei[E + e]], 1);
}

// per-block exclusive scan of g_deg -> g_off, block sums -> g_bsum
__global__ void scan1_kernel(int n) {
    __shared__ int wsum[8];
    __shared__ int wpre[8];
    int i = blockIdx.x * blockDim.x + threadIdx.x;
    int lane = threadIdx.x & 31, wid = threadIdx.x >> 5;
    int v = (i < n) ? g_deg[i] : 0;
    int incl = v;
    #pragma unroll
    for (int off = 1; off < 32; off <<= 1) {
        int t = __shfl_up_sync(0xffffffffu, incl, off);
        if (lane >= off) incl += t;
    }
    if (lane == 31) wsum[wid] = incl;
    __syncthreads();
    if (threadIdx.x == 0) {
        int run = 0;
        #pragma unroll
        for (int w = 0; w < 8; w++) { wpre[w] = run; run += wsum[w]; }
        g_bsum[blockIdx.x] = run;
    }
    __syncthreads();
    if (i < n) g_off[i] = wpre[wid] + incl - v;
}

// each block recomputes its block-sum prefix, adds it, inits cursors
__global__ void scan23_kernel(int nb, int n) {
    __shared__ int spre;
    if (threadIdx.x < 32) {
        int lane = threadIdx.x;
        int pre = 0, tot = 0;
        for (int i = lane; i < nb; i += 32) {
            int v = g_bsum[i];
            tot += v;
            if (i < (int)blockIdx.x) pre += v;
        }
        #pragma unroll
        for (int o = 16; o; o >>= 1) {
            pre += __shfl_xor_sync(0xffffffffu, pre, o);
            tot += __shfl_xor_sync(0xffffffffu, tot, o);
        }
        if (lane == 0) {
            spre = pre;
            if (blockIdx.x == 0) g_off[n] = tot;
        }
    }
    __syncthreads();
    int i = blockIdx.x * blockDim.x + threadIdx.x;
    if (i < n) {
        int v = g_off[i] + spre;
        g_off[i] = v;
        g_cur[i] = v;
    }
}

__global__ void fill_kernel(const int* __restrict__ ei, int E, int n) {
    int gt = blockIdx.x * blockDim.x + threadIdx.x;
    int gstride = gridDim.x * blockDim.x;
    int E8 = E >> 3;
    for (int q = gt; q < E8; q += gstride) {
        int4 sa = *(const int4*)&ei[q * 8];
        int4 sb = *(const int4*)&ei[q * 8 + 4];
        int4 da = *(const int4*)&ei[E + q * 8];
        int4 db = *(const int4*)&ei[E + q * 8 + 4];
        int p0 = atomicAdd(&g_cur[da.x], 1);
        int p1 = atomicAdd(&g_cur[da.y], 1);
        int p2 = atomicAdd(&g_cur[da.z], 1);
        int p3 = atomicAdd(&g_cur[da.w], 1);
        int p4 = atomicAdd(&g_cur[db.x], 1);
        int p5 = atomicAdd(&g_cur[db.y], 1);
        int p6 = atomicAdd(&g_cur[db.z], 1);
        int p7 = atomicAdd(&g_cur[db.w], 1);
        g_ssrc[p0] = sa.x;
        g_ssrc[p1] = sa.y;
        g_ssrc[p2] = sa.z;
        g_ssrc[p3] = sa.w;
        g_ssrc[p4] = sb.x;
        g_ssrc[p5] = sb.y;
        g_ssrc[p6] = sb.z;
        g_ssrc[p7] = sb.w;
    }
    for (int e = E8 * 8 + gt; e < E; e += gstride) {
        int p = atomicAdd(&g_cur[ei[E + e]], 1);
        g_ssrc[p] = ei[e];
    }
    for (int i = gt; i < n; i += gstride) {           // self-loops
        int p = atomicAdd(&g_cur[i], 1);
        g_ssrc[p] = i;
    }
}

// ---------------- tensor-core GEMM (HMMA m16n8k16) + fused alpha ----------------
template <int CIN>
__global__ __launch_bounds__(256, 3) void gemm_alpha_kernel(
        int sel, const float* __restrict__ avs, const float* __restrict__ avd, int n) {
    constexpr int CU = CIN / 8;
    __shared__ __half Xs[128 * CIN];
    __shared__ __half Ws[64 * CIN];

    const __half* Xh = (sel == 0) ? g_xh : g_oh;
    const __half* Wt = (sel == 0) ? g_wt1 : ((sel == 1) ? g_wt2 : g_wt3);

    int tid = threadIdx.x;
    int lane = tid & 31;
    int wid = tid >> 5;
    int m0 = blockIdx.x * 128;

    if (m0 + 128 <= n) {
        const uint4* src = (const uint4*)(Xh + (size_t)m0 * CIN);
        uint4* dst = (uint4*)Xs;
        #pragma unroll
        for (int i = 0; i < 128 * CU / 256; i++)
            dst[tid + i * 256] = src[tid + i * 256];
    } else {
        for (int idx = tid; idx < 128 * CU; idx += 256) {
            int row = idx / CU, u = idx - row * CU;
            int rowc = min(m0 + row, n - 1);
            *(uint4*)&Xs[(size_t)idx * 8] = *(const uint4*)&Xh[((size_t)rowc * CU + u) * 8];
        }
    }
    {
        const uint4* src = (const uint4*)Wt;
        uint4* dst = (uint4*)Ws;
        #pragma unroll
        for (int i = 0; i < 64 * CU / 256; i++)
            dst[tid + i * 256] = src[tid + i * 256];
    }
    __syncthreads();

    unsigned xsb;
    {
        unsigned long long t;
        asm("cvta.to.shared.u64 %0, %1;" : "=l"(t) : "l"(Xs)); xsb = (unsigned)t;
    }

    float c[8][4];
    #pragma unroll
    for (int t = 0; t < 8; t++) { c[t][0] = c[t][1] = c[t][2] = c[t][3] = 0.f; }

    int arow = lane & 15;
    int aub = lane >> 4;
    int bg = lane >> 2;
    int bw = lane & 3;

    #pragma unroll
    for (int ks = 0; ks < CIN / 16; ks++) {
        unsigned a0, a1, a2, a3;
        int au = (ks * 2 + aub) ^ (arow & 7);
        unsigned aaddr = xsb + ((wid * 16 + arow) * CU + au) * 16;
        asm volatile("ldmatrix.sync.aligned.m8n8.x4.shared.b16 {%0,%1,%2,%3}, [%4];"
                     : "=r"(a0), "=r"(a1), "=r"(a2), "=r"(a3) : "r"(aaddr));
        #pragma unroll
        for (int t = 0; t < 8; t++) {
            int nrow = t * 8 + bg;
            unsigned b0 = *(const unsigned*)((const char*)Ws +
                          ((nrow * CU + ((ks * 2) ^ bg)) * 16 + bw * 4));
            unsigned b1 = *(const unsigned*)((const char*)Ws +
                          ((nrow * CU + ((ks * 2 + 1) ^ bg)) * 16 + bw * 4));
            asm volatile("mma.sync.aligned.m16n8k16.row.col.f32.f16.f16.f32 "
                         "{%0,%1,%2,%3}, {%4,%5,%6,%7}, {%8,%9}, {%0,%1,%2,%3};"
                         : "+f"(c[t][0]), "+f"(c[t][1]), "+f"(c[t][2]), "+f"(c[t][3])
                         : "r"(a0), "r"(a1), "r"(a2), "r"(a3), "r"(b0), "r"(b1));
        }
    }

    int r0 = m0 + wid * 16 + (lane >> 2);
    int r1 = r0 + 8;
    float psA = 0.f, pdA = 0.f, psB = 0.f, pdB = 0.f;
    #pragma unroll
    for (int t = 0; t < 8; t++) {
        int col = t * 8 + (lane & 3) * 2;
        float as0 = avs[col], as1 = avs[col + 1];
        float ad0 = avd[col], ad1 = avd[col + 1];
        psA += c[t][0] * as0 + c[t][1] * as1;
        pdA += c[t][0] * ad0 + c[t][1] * ad1;
        psB += c[t][2] * as0 + c[t][3] * as1;
        pdB += c[t][2] * ad0 + c[t][3] * ad1;
        if (r0 < n)
            *(__half2*)((char*)g_h + ((size_t)r0 << 7) + col * 2) = __floats2half2_rn(c[t][0], c[t][1]);
        if (r1 < n)
            *(__half2*)((char*)g_h + ((size_t)r1 << 7) + col * 2) = __floats2half2_rn(c[t][2], c[t][3]);
    }
    #pragma unroll
    for (int o = 1; o <= 2; o <<= 1) {
        psA += __shfl_xor_sync(0xffffffffu, psA, o);
        pdA += __shfl_xor_sync(0xffffffffu, pdA, o);
        psB += __shfl_xor_sync(0xffffffffu, psB, o);
        pdB += __shfl_xor_sync(0xffffffffu, pdB, o);
    }
    if ((lane & 3) == 0) {
        if (r0 < n) { g_as[r0] = psA; g_ad[r0] = pdA; }
        if (r1 < n) { g_as[r1] = psB; g_ad[r1] = pdB; }
    }
}

// ---------------- segment softmax + weighted aggregation (fp16 gather) ----------------
__global__ void agg_kernel(const float* __restrict__ bias,
                           float* __restrict__ dout, int n, int mode) {
    int lane = threadIdx.x & 31;
    int qid = lane >> 3;
    int q = lane & 7;
    int gw = (blockIdx.x * blockDim.x + threadIdx.x) >> 5;
    int nw = (gridDim.x * blockDim.x) >> 5;

    for (int d = gw; d < n; d += nw) {
        int beg = g_off[d], end = g_off[d + 1];
        float adv = g_ad[d];

        float acc[8];
        #pragma unroll
        for (int i = 0; i < 8; i++) acc[i] = 0.f;
        float denp = 0.f;

        for (int base = beg; base < end; base += 32) {
            int j = base + lane;
            int s = 0;
            float w = 0.f;
            if (j < end) {
                s = g_ssrc[j];
                float e = g_as[s] + adv;
                e = e > 0.f ? e : 0.2f * e;
                w = __expf(e);
            }
            denp += w;
            int cnt = min(32, end - base);
            #pragma unroll 4
            for (int k = 0; k < cnt; k += 4) {
                int e = k + qid;
                int   sk = __shfl_sync(0xffffffffu, s, e & 31);
                float wk = __shfl_sync(0xffffffffu, w, e & 31);
                if (e >= cnt) wk = 0.f;
                uint4 u = *(const uint4*)((const char*)g_h + ((size_t)sk << 7) + (q << 4));
                float2 f0 = __half22float2(*(__half2*)&u.x);
                float2 f1 = __half22float2(*(__half2*)&u.y);
                float2 f2 = __half22float2(*(__half2*)&u.z);
                float2 f3 = __half22float2(*(__half2*)&u.w);
                acc[0] = fmaf(wk, f0.x, acc[0]);
                acc[1] = fmaf(wk, f0.y, acc[1]);
                acc[2] = fmaf(wk, f1.x, acc[2]);
                acc[3] = fmaf(wk, f1.y, acc[3]);
                acc[4] = fmaf(wk, f2.x, acc[4]);
                acc[5] = fmaf(wk, f2.y, acc[5]);
                acc[6] = fmaf(wk, f3.x, acc[6]);
                acc[7] = fmaf(wk, f3.y, acc[7]);
            }
        }
        #pragma unroll
        for (int i = 0; i < 8; i++) {
            acc[i] += __shfl_xor_sync(0xffffffffu, acc[i], 8);
            acc[i] += __shfl_xor_sync(0xffffffffu, acc[i], 16);
        }
        float den = denp;
        #pragma unroll
        for (int o = 16; o; o >>= 1) den += __shfl_xor_sync(0xffffffffu, den, o);

        if (qid == 0) {
            float inv = 1.f / den;
            const float4* b4 = (const float4*)bias;
            float4 bv0 = b4[q * 2], bv1 = b4[q * 2 + 1];
            float4 o0, o1;
            o0.x = acc[0] * inv + bv0.x;
            o0.y = acc[1] * inv + bv0.y;
            o0.z = acc[2] * inv + bv0.z;
            o0.w = acc[3] * inv + bv0.w;
            o1.x = acc[4] * inv + bv1.x;
            o1.y = acc[5] * inv + bv1.y;
            o1.z = acc[6] * inv + bv1.z;
            o1.w = acc[7] * inv + bv1.w;
            if (mode == 0) {  // ELU -> fp16 pre-swizzled g_oh
                o0.x = o0.x > 0.f ? o0.x : (__expf(o0.x) - 1.f);
                o0.y = o0.y > 0.f ? o0.y : (__expf(o0.y) - 1.f);
                o0.z = o0.z > 0.f ? o0.z : (__expf(o0.z) - 1.f);
                o0.w = o0.w > 0.f ? o0.w : (__expf(o0.w) - 1.f);
                o1.x = o1.x > 0.f ? o1.x : (__expf(o1.x) - 1.f);
                o1.y = o1.y > 0.f ? o1.y : (__expf(o1.y) - 1.f);
                o1.z = o1.z > 0.f ? o1.z : (__expf(o1.z) - 1.f);
                o1.w = o1.w > 0.f ? o1.w : (__expf(o1.w) - 1.f);
                union { __half2 h[4]; uint4 qv; } ph;
                ph.h[0] = __floats2half2_rn(o0.x, o0.y);
                ph.h[1] = __floats2half2_rn(o0.z, o0.w);
                ph.h[2] = __floats2half2_rn(o1.x, o1.y);
                ph.h[3] = __floats2half2_rn(o1.z, o1.w);
                *(uint4*)&g_oh[((size_t)d * 8 + (q ^ (d & 7))) * 8] = ph.qv;
            } else {
                float4* orow = (float4*)(dout + (size_t)d * CH);
                orow[q * 2]     = o0;
                orow[q * 2 + 1] = o1;
            }
        }
    }
}

// ---------------- launch ----------------
extern "C" void kernel_launch(void* const* d_in, const int* in_sizes, int n_in,
                              void* d_out, int out_size) {
    const float* x     = (const float*)d_in[0];
    const int*   ei    = (const int*)d_in[1];
    const float* W1    = (const float*)d_in[2];
    const float* asr1  = (const float*)d_in[3];
    const float* adt1  = (const float*)d_in[4];
    const float* b1    = (const float*)d_in[5];
    const float* W2    = (const float*)d_in[6];
    const float* asr2  = (const float*)d_in[7];
    const float* adt2  = (const float*)d_in[8];
    const float* b2    = (const float*)d_in[9];
    const float* W3    = (const float*)d_in[10];
    const float* asr3  = (const float*)d_in[11];
    const float* adt3  = (const float*)d_in[12];
    const float* b3    = (const float*)d_in[13];

    int n = in_sizes[0] / 128;   // 50000
    int E = in_sizes[1] / 2;     // 800000
    float* dout = (float*)d_out;

    int nb = (n + 255) / 256;
    int aggGrid = (n * 32 + 255) / 256;
    int gemmGrid = (n + 127) / 128;

    bool two = g_fork_ok;
    cudaStream_t s2 = two ? g_s2 : (cudaStream_t)0;

    if (two) {
        cudaEventRecord(g_ef, 0);
        cudaStreamWaitEvent(s2, g_ef, 0);
    }
    // CSR chain
    zero_kernel<<<96, 256, 0, s2>>>(n);
    count_kernel<<<832, 256, 0, s2>>>(ei, E, n);
    scan1_kernel<<<nb, 256, 0, s2>>>(n);
    scan23_kernel<<<nb, 256, 0, s2>>>(nb, n);
    fill_kernel<<<832, 256, 0, s2>>>(ei, E, n);
    if (two) cudaEventRecord(g_ej, s2);

    // main stream: conversion + layer-1 GEMM (independent of CSR)
    conv_kernel<<<416, 256>>>(x, W1, W2, W3, n);
    gemm_alpha_kernel<128><<<gemmGrid, 256>>>(0, asr1, adt1, n);

    if (two) cudaStreamWaitEvent(0, g_ej, 0);

    agg_kernel<<<aggGrid, 256>>>(b1, dout, n, 0);
    gemm_alpha_kernel<64><<<gemmGrid, 256>>>(1, asr2, adt2, n);
    agg_kernel<<<aggGrid, 256>>>(b2, dout, n, 0);
    gemm_alpha_kernel<64><<<gemmGrid, 256>>>(2, asr3, adt3, n);
    agg_kernel<<<aggGrid, 256>>>(b3, dout, n, 1);
}